// round 15
// baseline (speedup 1.0000x reference)
#include <cuda_runtime.h>
#include <cstdint>

#define OUTD 11008
#define IND  4096
#define GCNT 704512
#define CDIM 172
#define NB   8
#define ICHUNK 512
#define NIT  4                      /* 128 groups per iter (4 per lane, int4) */

typedef unsigned long long ull;
typedef unsigned int u32;

// ---------------------------------------------------------------------------
__global__ void init_out_kernel(const float* __restrict__ bias,
                                float* __restrict__ out) {
    int idx = blockIdx.x * blockDim.x + threadIdx.x;
    if (idx < NB * OUTD) out[idx] = bias[idx % OUTD];
}

// packed f32x2 helpers (sm_100+)
__device__ __forceinline__ void fma2(ull& acc, ull a, ull b) {
    asm("fma.rn.f32x2 %0, %1, %2, %0;" : "+l"(acc) : "l"(a), "l"(b));
}
__device__ __forceinline__ ull add2(ull a, ull b) {
    ull r; asm("add.rn.f32x2 %0, %1, %2;" : "=l"(r) : "l"(a), "l"(b)); return r;
}
__device__ __forceinline__ ull pack2(float v) {
    ull r; asm("mov.b64 %0, {%1, %1};" : "=l"(r) : "f"(v)); return r;
}
__device__ __forceinline__ ull pack2f(float a, float b) {
    ull r; asm("mov.b64 %0, {%1, %2};" : "=l"(r) : "f"(a), "f"(b)); return r;
}
__device__ __forceinline__ ull pack2u(u32 a, u32 b) {
    ull r; asm("mov.b64 %0, {%1, %2};" : "=l"(r) : "r"(a), "r"(b)); return r;
}

// ---------------------------------------------------------------------------
// Main kernel. Block = (c, i-chunk of 512). Warp w owns Wq rows 4w..4w+3
// (8 output rows via hi/lo nibbles). x is staged PRE-SCALED and DUPLICATED
// ({y,y} per batch) so weights dequant straight into f32x2 pairs {nl,nh}:
// per byte = 2 LOP3 + 1 MOV64 + 1 ADD2 + 8 FFMA2. Zero-point term T[c,b]
// is accumulated chunk-partially during staging, subtracted in the epilogue.
// ---------------------------------------------------------------------------
__global__ __launch_bounds__(256, 2) void hqq_gemv_kernel(
    const int*   __restrict__ Wq,     // [32, 704512] int32 (one byte per elem)
    const float* __restrict__ scale,  // [704512]
    const float* __restrict__ zero,   // [704512]
    const float* __restrict__ x,      // [8, 4096]
    float*       __restrict__ out)    // [8, 11008]
{
    // Pair-interleaved dup planes: uint4 entry pe = (jo*4+bp)*128 + (j>>2)
    // holds {y[2bp][j], y[2bp][j], y[2bp+1][j], y[2bp+1][j]}, j = (pe&127)*4+jo.
    // Main loop reads lane-consecutive LDS.128 -> conflict-free.
    __shared__ __align__(16) ull xsm[4096];            // 32 KB
    __shared__ ull tzsm[16];                           // T partials [bp][w&3]

    const int tid = threadIdx.x;
    const int h   = blockIdx.x & 7;                    // i-chunk
    const int c   = blockIdx.x >> 3;                   // 0..171
    const int ib  = h * ICHUNK;

    const int w  = tid >> 5;                           // warp 0..7
    const int l  = tid & 31;
    const int t7 = tid >> 7;                           // 0/1: bp parity class

    // ---- staging + chunk-partial T accumulation -------------------------
    ull tz0 = 0ull, tz1 = 0ull;                        // bp = t7 / t7+2
    #pragma unroll
    for (int r = 0; r < 8; ++r) {                      // 2048 uint4 entries
        const int pe    = tid + (r << 8);
        const int plane = pe >> 7, m = pe & 127;
        const int jo    = plane >> 2, bp = plane & 3;
        const int j     = (m << 2) | jo;
        const int gi    = c * IND + ib + j;
        const float sv  = __ldg(scale + gi);
        const float zv  = __ldg(zero  + gi);
        const float yl  = __ldg(x + (2 * bp)     * IND + ib + j) * sv;
        const float yh  = __ldg(x + (2 * bp + 1) * IND + ib + j) * sv;
        reinterpret_cast<float4*>(xsm)[pe] = make_float4(yl, yl, yh, yh);
        const ull yp = pack2f(yl, yh);
        if ((r & 1) == 0) fma2(tz0, pack2(zv), yp);
        else              fma2(tz1, pack2(zv), yp);
    }
    #pragma unroll
    for (int d = 16; d >= 1; d >>= 1) {
        tz0 = add2(tz0, __shfl_xor_sync(0xffffffffu, tz0, d));
        tz1 = add2(tz1, __shfl_xor_sync(0xffffffffu, tz1, d));
    }
    if (l == 0) {
        tzsm[t7 * 4 + (w & 3)]       = tz0;            // bp = t7
        tzsm[(t7 + 2) * 4 + (w & 3)] = tz1;            // bp = t7+2
    }
    __syncthreads();

    // ---- main loop ------------------------------------------------------
    const int wrow = w << 2;                           // Wq rows wrow..wrow+3
    const int g0   = c * IND + ib;

    const int4* qp0 = (const int4*)(Wq + (long)(wrow + 0) * GCNT + g0) + l;
    const int4* qp1 = (const int4*)(Wq + (long)(wrow + 1) * GCNT + g0) + l;
    const int4* qp2 = (const int4*)(Wq + (long)(wrow + 2) * GCNT + g0) + l;
    const int4* qp3 = (const int4*)(Wq + (long)(wrow + 3) * GCNT + g0) + l;

    const ull csub = pack2f(-8388608.f, -524288.f);    // {-2^23, -2^19}

    ull acc[32];                                       // acc[r*8+b] = {lo,hi}
    #pragma unroll
    for (int i = 0; i < 32; ++i) acc[i] = 0ull;

    int4 qa = __ldg(qp0), qb = __ldg(qp1), qc = __ldg(qp2), qd = __ldg(qp3);

    #pragma unroll
    for (int it = 0; it < NIT; ++it) {
        const int off = (it + 1 < NIT) ? (it + 1) * 32 : 0;
        int4 qan = __ldg(qp0 + off), qbn = __ldg(qp1 + off);
        int4 qcn = __ldg(qp2 + off), qdn = __ldg(qp3 + off);

        const int qra[4] = {qa.x, qa.y, qa.z, qa.w};
        const int qrb[4] = {qb.x, qb.y, qb.z, qb.w};
        const int qrc[4] = {qc.x, qc.y, qc.z, qc.w};
        const int qrd[4] = {qd.x, qd.y, qd.z, qd.w};

        #pragma unroll
        for (int jo = 0; jo < 4; ++jo) {               // substep = one group
            const ulonglong2* xq = reinterpret_cast<const ulonglong2*>(xsm)
                                 + (jo * 4) * 128 + it * 32 + l;
            const ulonglong2 p0 = xq[0],   p1 = xq[128];
            const ulonglong2 p2 = xq[256], p3 = xq[384];

            // wv = {nl, nh} exact: lo via 2^23 magic, hi via 2^19 magic.
#define DOROW(QV, R)                                                           \
            {                                                                  \
                u32 vlo = ((u32)(QV) & 0x0Fu) | 0x4B000000u;                   \
                u32 vhi = ((u32)(QV) & 0xF0u) | 0x49000000u;                   \
                ull wv = add2(pack2u(vlo, vhi), csub);                         \
                fma2(acc[(R)*8 + 0], p0.x, wv); fma2(acc[(R)*8 + 1], p0.y, wv);\
                fma2(acc[(R)*8 + 2], p1.x, wv); fma2(acc[(R)*8 + 3], p1.y, wv);\
                fma2(acc[(R)*8 + 4], p2.x, wv); fma2(acc[(R)*8 + 5], p2.y, wv);\
                fma2(acc[(R)*8 + 6], p3.x, wv); fma2(acc[(R)*8 + 7], p3.y, wv);\
            }
            DOROW(qra[jo], 0) DOROW(qrb[jo], 1) DOROW(qrc[jo], 2) DOROW(qrd[jo], 3)
#undef DOROW
        }

        qa = qan; qb = qbn; qc = qcn; qd = qdn;
    }

    // Butterfly halving exchange: 32 f32x2 per lane -> lane l holds item l
    // summed over all 32 lanes. item k: r = k>>3 (warp row), b = k&7 (batch).
    #pragma unroll
    for (int d = 16; d >= 1; d >>= 1) {
        const bool up = (l & d) != 0;
        #pragma unroll
        for (int k = 0; k < d; ++k) {
            ull send = up ? acc[k] : acc[k + d];
            ull got  = __shfl_xor_sync(0xffffffffu, send, d);
            ull keep = up ? acc[k + d] : acc[k];
            acc[k] = add2(keep, got);
        }
    }

    // ---- epilogue: subtract chunk-partial T, atomic merge ---------------
    const int r = l >> 3, b = l & 7, bp = b >> 1;

    ull tzp = tzsm[bp * 4];
    #pragma unroll
    for (int k = 1; k < 4; ++k) tzp = add2(tzp, tzsm[bp * 4 + k]);

    float flo, fhi, tx, ty;
    asm("mov.b64 {%0, %1}, %2;" : "=f"(flo), "=f"(fhi) : "l"(acc[0]));
    asm("mov.b64 {%0, %1}, %2;" : "=f"(tx),  "=f"(ty)  : "l"(tzp));
    const float tval = (b & 1) ? ty : tx;

    const int o_hi = (wrow + r) * CDIM + c;            // hi-nibble row
    atomicAdd(out + b * OUTD + o_hi,             fhi - tval);
    atomicAdd(out + b * OUTD + o_hi + 32 * CDIM, flo - tval);
}

// ---------------------------------------------------------------------------
extern "C" void kernel_launch(void* const* d_in, const int* in_sizes, int n_in,
                              void* d_out, int out_size) {
    const int*   Wq    = (const int*)  d_in[0];
    const float* scale = (const float*)d_in[1];
    const float* zero  = (const float*)d_in[2];
    const float* x     = (const float*)d_in[3];
    const float* bias  = (const float*)d_in[4];
    float* out = (float*)d_out;

    init_out_kernel<<<(NB * OUTD + 255) / 256, 256>>>(bias, out);
    hqq_gemv_kernel<<<CDIM * (IND / ICHUNK), 256>>>(Wq, scale, zero, x, out);
}